// round 9
// baseline (speedup 1.0000x reference)
#include <cuda_runtime.h>
#include <math.h>

// Problem constants
constexpr int B   = 8;
constexpr int R   = 128;
constexpr int H   = 256;
constexpr int IND = 512;
constexpr int L   = 3;
constexpr int NH  = 4;
constexpr int DH  = 64;

constexpr int SZ = B * R * H;  // 262144
constexpr int HH = H * H;

// Scratch layout
constexpr int OFF_H    = 0;
constexpr int OFF_AACT = SZ;
constexpr int OFF_BB   = 2 * SZ;
constexpr int OFF_AGG  = 3 * SZ;
constexpr int OFF_HU   = 4 * SZ;
constexpr int OFF_UPRE = 5 * SZ;
constexpr int OFF_U    = 6 * SZ;
constexpr int OFF_Q    = 7 * SZ;
constexpr int OFF_K    = 8 * SZ;
constexpr int OFF_V    = 9 * SZ;
constexpr int OFF_AO   = 10 * SZ;
constexpr int OFF_ADJ  = 11 * SZ;                 // R*R
constexpr int OFF_RS   = OFF_ADJ + R * R;         // R
constexpr int OFF_W2U  = OFF_RS + R;              // L*H*H
constexpr int OFF_C2   = OFF_W2U + L * HH;        // L*H
constexpr int TOTAL    = OFF_C2 + L * H;

__device__ float g_buf[TOTAL];

typedef unsigned long long u64;

__device__ __forceinline__ u64 pack2(float x) {
    u64 r; asm("mov.b64 %0, {%1, %1};" : "=l"(r) : "f"(x)); return r;
}
__device__ __forceinline__ void fma2(u64& d, u64 a, u64 b) {
    asm("fma.rn.f32x2 %0, %1, %2, %0;" : "+l"(d) : "l"(a), "l"(b));
}
__device__ __forceinline__ float2 unpack2(u64 v) {
    float2 f; asm("mov.b64 {%0, %1}, %2;" : "=f"(f.x), "=f"(f.y) : "l"(v)); return f;
}

struct GemmJob {
    const float* A;
    const float* W;
    const float* bias;    // [256] or null
    const float* rowv;    // [128] or null (indexed m & 127)
    const float* colv;    // [256] (with rowv)
    const float* addend;  // [M,256] or null
    float* C;
    int relu;
};

// ---------------------------------------------------------------------------
// tf32 helpers
__device__ __forceinline__ void tf32split(float x, float& hi, float& lo) {
    unsigned h;
    asm("cvt.rna.tf32.f32 %0, %1;" : "=r"(h) : "f"(x));
    hi = __uint_as_float(h);
    float r = x - hi;
    unsigned l;
    asm("cvt.rna.tf32.f32 %0, %1;" : "=r"(l) : "f"(r));
    lo = __uint_as_float(l);
}

__device__ __forceinline__ void mma8(float4& d, const float* a, float b0f, float b1f) {
    asm("mma.sync.aligned.m16n8k8.row.col.f32.tf32.tf32.f32 "
        "{%0,%1,%2,%3}, {%4,%5,%6,%7}, {%8,%9}, {%0,%1,%2,%3};"
        : "+f"(d.x), "+f"(d.y), "+f"(d.z), "+f"(d.w)
        : "r"(__float_as_uint(a[0])), "r"(__float_as_uint(a[1])),
          "r"(__float_as_uint(a[2])), "r"(__float_as_uint(a[3])),
          "r"(__float_as_uint(b0f)), "r"(__float_as_uint(b1f)));
}

// ---------------------------------------------------------------------------
// TF32 GEMM: BM=32, BN=64, BK=16, 256 threads (8 warps = 2m x 4n, warp 16x16).
// C = act(A@W [+addend] [+bias] [+rowv[m&127]*colv]); K = 256 fixed.
// 3xTF32 split: A@W ~= Ah@Wh + Ah@Wl + Al@Wh  (fp32-grade accuracy).
__global__ __launch_bounds__(256) void gemm_tf32_kernel(GemmJob j0, GemmJob j1, GemmJob j2) {
    __shared__ float Ah[2][16][36], Al[2][16][36];
    __shared__ float Wh[2][16][68], Wl[2][16][68];

    const GemmJob& job = (blockIdx.z == 0) ? j0 : ((blockIdx.z == 1) ? j1 : j2);
    const float* __restrict__ A = job.A;
    const float* __restrict__ W = job.W;
    const int m0 = blockIdx.y * 32, n0 = blockIdx.x * 64;
    const int t = threadIdx.x;
    const int lane = t & 31, w = t >> 5;
    const int mw = (w & 1) * 16;         // warp m offset in tile
    const int nw = (w >> 1) * 16;        // warp n offset in tile
    const int g = lane >> 2, tig = lane & 3;

    // loader maps
    const int arow = t >> 2, ak4 = (t & 3) * 4;     // A: threads 0..127
    const int wk = t >> 4, wn4 = (t & 15) * 4;      // W: all 256

    float4 acc[2];
    acc[0] = make_float4(0.f, 0.f, 0.f, 0.f);
    acc[1] = make_float4(0.f, 0.f, 0.f, 0.f);

    const bool aload = (t < 128);
    const float* Aptr = A + (m0 + arow) * 256 + ak4;
    const float* Wptr = W + wk * 256 + n0 + wn4;

    // prologue: tile 0
    float4 aR, wR;
    if (aload) aR = *(const float4*)Aptr;
    wR = *(const float4*)Wptr;
    {
        if (aload) {
            float hi, lo;
            tf32split(aR.x, hi, lo); Ah[0][ak4 + 0][arow] = hi; Al[0][ak4 + 0][arow] = lo;
            tf32split(aR.y, hi, lo); Ah[0][ak4 + 1][arow] = hi; Al[0][ak4 + 1][arow] = lo;
            tf32split(aR.z, hi, lo); Ah[0][ak4 + 2][arow] = hi; Al[0][ak4 + 2][arow] = lo;
            tf32split(aR.w, hi, lo); Ah[0][ak4 + 3][arow] = hi; Al[0][ak4 + 3][arow] = lo;
        }
        float4 whi, wlo;
        tf32split(wR.x, whi.x, wlo.x); tf32split(wR.y, whi.y, wlo.y);
        tf32split(wR.z, whi.z, wlo.z); tf32split(wR.w, whi.w, wlo.w);
        *(float4*)&Wh[0][wk][wn4] = whi;
        *(float4*)&Wl[0][wk][wn4] = wlo;
    }
    __syncthreads();

    #pragma unroll 1
    for (int kt = 0; kt < 16; kt++) {
        const int buf = kt & 1;
        if (kt < 15) {
            if (aload) aR = *(const float4*)(Aptr + (kt + 1) * 16);
            wR = *(const float4*)(Wptr + (kt + 1) * 16 * 256);
        }
        // compute on buf: 2 k8 steps
        #pragma unroll
        for (int s = 0; s < 2; s++) {
            const int kb = s * 8;
            float ah[4], al[4];
            ah[0] = Ah[buf][kb + tig][mw + g];
            ah[1] = Ah[buf][kb + tig][mw + g + 8];
            ah[2] = Ah[buf][kb + tig + 4][mw + g];
            ah[3] = Ah[buf][kb + tig + 4][mw + g + 8];
            al[0] = Al[buf][kb + tig][mw + g];
            al[1] = Al[buf][kb + tig][mw + g + 8];
            al[2] = Al[buf][kb + tig + 4][mw + g];
            al[3] = Al[buf][kb + tig + 4][mw + g + 8];
            #pragma unroll
            for (int nt = 0; nt < 2; nt++) {
                const int nn = nw + nt * 8 + g;
                float bh0 = Wh[buf][kb + tig][nn];
                float bh1 = Wh[buf][kb + tig + 4][nn];
                float bl0 = Wl[buf][kb + tig][nn];
                float bl1 = Wl[buf][kb + tig + 4][nn];
                mma8(acc[nt], al, bh0, bh1);
                mma8(acc[nt], ah, bl0, bl1);
                mma8(acc[nt], ah, bh0, bh1);
            }
        }
        if (kt < 15) {
            const int nxt = buf ^ 1;
            if (aload) {
                float hi, lo;
                tf32split(aR.x, hi, lo); Ah[nxt][ak4 + 0][arow] = hi; Al[nxt][ak4 + 0][arow] = lo;
                tf32split(aR.y, hi, lo); Ah[nxt][ak4 + 1][arow] = hi; Al[nxt][ak4 + 1][arow] = lo;
                tf32split(aR.z, hi, lo); Ah[nxt][ak4 + 2][arow] = hi; Al[nxt][ak4 + 2][arow] = lo;
                tf32split(aR.w, hi, lo); Ah[nxt][ak4 + 3][arow] = hi; Al[nxt][ak4 + 3][arow] = lo;
            }
            float4 whi, wlo;
            tf32split(wR.x, whi.x, wlo.x); tf32split(wR.y, whi.y, wlo.y);
            tf32split(wR.z, whi.z, wlo.z); tf32split(wR.w, whi.w, wlo.w);
            *(float4*)&Wh[nxt][wk][wn4] = whi;
            *(float4*)&Wl[nxt][wk][wn4] = wlo;
        }
        __syncthreads();
    }

    // epilogue: acc[nt]: rows (m0+mw+g, +8), cols (n0+nw+nt*8+2*tig, +1)
    #pragma unroll
    for (int nt = 0; nt < 2; nt++) {
        const int c = n0 + nw + nt * 8 + 2 * tig;
        float2 vtop = make_float2(acc[nt].x, acc[nt].y);
        float2 vbot = make_float2(acc[nt].z, acc[nt].w);
        #pragma unroll
        for (int half = 0; half < 2; half++) {
            const int r = m0 + mw + g + half * 8;
            float2 v = half ? vbot : vtop;
            if (job.addend) {
                float2 ad = *(const float2*)&job.addend[r * 256 + c];
                v.x += ad.x; v.y += ad.y;
            }
            if (job.bias) {
                float2 bi = *(const float2*)&job.bias[c];
                v.x += bi.x; v.y += bi.y;
            }
            if (job.rowv) {
                float rv = job.rowv[r & (R - 1)];
                float2 cv = *(const float2*)&job.colv[c];
                v.x += rv * cv.x; v.y += rv * cv.y;
            }
            if (job.relu) { v.x = fmaxf(v.x, 0.f); v.y = fmaxf(v.y, 0.f); }
            *(float2*)&job.C[r * 256 + c] = v;
        }
    }
}

// ---------------------------------------------------------------------------
// Round-3 proven FFMA GEMM tile (device fn) — used only inside setup_kernel.
constexpr int G3_SH = 2 * 32 * 36 + 2 * 32 * 64;  // 6400

__device__ __forceinline__ void g3_tile(const GemmJob& job, int m0, int n0, float* sh) {
    float* AsBuf = sh;
    float* WsBuf = sh + 2 * 32 * 36;
    const float* __restrict__ A = job.A;
    const float* __restrict__ W = job.W;
    const int tid = threadIdx.x;
    const int tx = tid & 15, ty = tid >> 4;
    const int ar = tid >> 3, ac4 = (tid & 7) * 4;
    const int wc0 = tid >> 4, wn0 = (tid & 15) * 4;
    const int wc1 = (tid + 256) >> 4, wn1 = wn0;

    u64 acc[2][2];
    acc[0][0] = acc[0][1] = acc[1][0] = acc[1][1] = 0ull;

    float4 aR = *(const float4*)&A[(m0 + ar) * 256 + ac4];
    float4 wR0 = *(const float4*)&W[wc0 * 256 + n0 + wn0];
    float4 wR1 = *(const float4*)&W[wc1 * 256 + n0 + wn1];
    *(float4*)&AsBuf[ar * 36 + ac4] = aR;
    *(float4*)&WsBuf[wc0 * 64 + wn0] = wR0;
    *(float4*)&WsBuf[wc1 * 64 + wn1] = wR1;
    __syncthreads();

    #pragma unroll 1
    for (int t = 0; t < 8; t++) {
        const int cur = t & 1;
        const bool has_next = (t < 7);
        if (has_next) {
            const int k0 = (t + 1) * 32;
            aR  = *(const float4*)&A[(m0 + ar) * 256 + k0 + ac4];
            wR0 = *(const float4*)&W[(k0 + wc0) * 256 + n0 + wn0];
            wR1 = *(const float4*)&W[(k0 + wc1) * 256 + n0 + wn1];
        }
        const float* __restrict__ as = AsBuf + cur * (32 * 36);
        const float* __restrict__ ws = WsBuf + cur * (32 * 64);
        #pragma unroll
        for (int kk = 0; kk < 32; kk++) {
            ulonglong2 bv = *(const ulonglong2*)&ws[kk * 64 + tx * 4];
            u64 pa0 = pack2(as[(ty * 2 + 0) * 36 + kk]);
            u64 pa1 = pack2(as[(ty * 2 + 1) * 36 + kk]);
            fma2(acc[0][0], pa0, bv.x);
            fma2(acc[0][1], pa0, bv.y);
            fma2(acc[1][0], pa1, bv.x);
            fma2(acc[1][1], pa1, bv.y);
        }
        if (has_next) {
            const int nxt = cur ^ 1;
            *(float4*)&AsBuf[nxt * (32 * 36) + ar * 36 + ac4] = aR;
            *(float4*)&WsBuf[nxt * (32 * 64) + wc0 * 64 + wn0] = wR0;
            *(float4*)&WsBuf[nxt * (32 * 64) + wc1 * 64 + wn1] = wR1;
        }
        __syncthreads();
    }

    const int n = n0 + tx * 4;
    #pragma unroll
    for (int i = 0; i < 2; i++) {
        const int m = m0 + ty * 2 + i;
        float2 p0 = unpack2(acc[i][0]);
        float2 p1 = unpack2(acc[i][1]);
        float4 v = make_float4(p0.x, p0.y, p1.x, p1.y);
        *(float4*)&job.C[m * 256 + n] = v;
    }
}

// ---------------------------------------------------------------------------
// Setup: 0..95 -> W2u tiles ; 96..111 -> prep_A ; 112..119 -> h0 ; 120..122 -> c2
__global__ __launch_bounds__(256) void setup_kernel(
    const float* __restrict__ rule_adj, float* __restrict__ A, float* __restrict__ rowsum,
    const float* __restrict__ x, const float* __restrict__ We,
    const float* __restrict__ be, float* __restrict__ h,
    const float* __restrict__ msg_b2, const float* __restrict__ msg_W2,
    const float* __restrict__ upd_W1, float* __restrict__ w2u, float* __restrict__ c2)
{
    __shared__ float sh[G3_SH];
    int bid = blockIdx.x, t = threadIdx.x;
    if (bid < 96) {
        int l = bid >> 5, rem = bid & 31;
        GemmJob j;
        j.A = msg_W2 + l * HH; j.W = upd_W1 + l * 2 * HH + HH;
        j.bias = nullptr; j.rowv = nullptr; j.colv = nullptr; j.addend = nullptr;
        j.C = w2u + l * HH; j.relu = 0;
        g3_tile(j, (rem >> 2) * 32, (rem & 3) * 64, sh);
    } else if (bid < 112) {
        int wid = t >> 5, lane = t & 31;
        int i = (bid - 96) * 8 + wid;
        float4 va = *(const float4*)&rule_adj[i * R + lane * 4];
        float s0 = 1.f / (1.f + expf(-va.x));
        float s1 = 1.f / (1.f + expf(-va.y));
        float s2 = 1.f / (1.f + expf(-va.z));
        float s3 = 1.f / (1.f + expf(-va.w));
        int c = lane * 4;
        if (i == c + 0) s0 = 0.f;
        if (i == c + 1) s1 = 0.f;
        if (i == c + 2) s2 = 0.f;
        if (i == c + 3) s3 = 0.f;
        *(float4*)&A[i * R + c] = make_float4(s0, s1, s2, s3);
        float part = s0 + s1 + s2 + s3;
        for (int o = 16; o; o >>= 1) part += __shfl_xor_sync(0xffffffffu, part, o);
        if (lane == 0) rowsum[i] = part;
    } else if (bid < 120) {
        int b = bid - 112;
        float* xs = sh;
        xs[t]       = x[b * IND + t];
        xs[t + 256] = x[b * IND + 256 + t];
        __syncthreads();
        float acc = be[t];
        #pragma unroll 8
        for (int k = 0; k < IND; k++) acc += xs[k] * We[k * H + t];
        for (int r = 0; r < R; r++) h[(b * R + r) * H + t] = acc;
    } else {
        int l = bid - 120;
        float* bs = sh;
        bs[t] = msg_b2[l * H + t];
        __syncthreads();
        const float* W = upd_W1 + l * 2 * HH + HH;
        float acc = 0.f;
        #pragma unroll 8
        for (int k = 0; k < H; k++) acc += bs[k] * W[k * H + t];
        c2[l * H + t] = acc;
    }
}

// ---------------------------------------------------------------------------
// aggpre[b,i,h] = sum_j A[i,j] * relu(a[b,i,h] + bb[b,j,h])   (b1 folded into bb)
__global__ __launch_bounds__(256) void agg_kernel(
    const float* __restrict__ a, const float* __restrict__ bbg,
    const float* __restrict__ A, float* __restrict__ out)
{
    __shared__ float bbs[128 * 64];
    int hc = blockIdx.x * 64, ic = blockIdx.y * 32, b = blockIdx.z;
    int t = threadIdx.x;
    const float* bp = bbg + b * R * H;
    for (int idx = t; idx < 2048; idx += 256) {
        int j = idx >> 4, c4 = (idx & 15) * 4;
        *(float4*)&bbs[j * 64 + c4] = *(const float4*)&bp[j * H + hc + c4];
    }
    __syncthreads();
    int hl = (t & 15) * 4;
    int i0 = ic + (t >> 4) * 2;
    float4 av0 = *(const float4*)&a[(b * R + i0) * H + hc + hl];
    float4 av1 = *(const float4*)&a[(b * R + i0 + 1) * H + hc + hl];
    float4 ac0 = {0, 0, 0, 0}, ac1 = {0, 0, 0, 0};
    const float* Ar = A + i0 * R;
    #pragma unroll 4
    for (int j = 0; j < R; j++) {
        float4 bv = *(const float4*)&bbs[j * 64 + hl];
        float w0 = __ldg(&Ar[j]);
        float w1 = __ldg(&Ar[R + j]);
        ac0.x += w0 * fmaxf(av0.x + bv.x, 0.f);
        ac0.y += w0 * fmaxf(av0.y + bv.y, 0.f);
        ac0.z += w0 * fmaxf(av0.z + bv.z, 0.f);
        ac0.w += w0 * fmaxf(av0.w + bv.w, 0.f);
        ac1.x += w1 * fmaxf(av1.x + bv.x, 0.f);
        ac1.y += w1 * fmaxf(av1.y + bv.y, 0.f);
        ac1.z += w1 * fmaxf(av1.z + bv.z, 0.f);
        ac1.w += w1 * fmaxf(av1.w + bv.w, 0.f);
    }
    *(float4*)&out[(b * R + i0) * H + hc + hl]     = ac0;
    *(float4*)&out[(b * R + i0 + 1) * H + hc + hl] = ac1;
}

// ---------------------------------------------------------------------------
// h = LayerNorm(h + u) * g + beta
__global__ void ln_kernel(float* __restrict__ h, const float* __restrict__ u,
                          const float* __restrict__ gg, const float* __restrict__ bb) {
    __shared__ float red[8];
    int row = blockIdx.x, t = threadIdx.x;
    int o = row * H + t;
    float x = h[o] + u[o];
    float s = x;
    for (int k = 16; k; k >>= 1) s += __shfl_xor_sync(0xffffffffu, s, k);
    if ((t & 31) == 0) red[t >> 5] = s;
    __syncthreads();
    if (t < 32) {
        float v = (t < 8) ? red[t] : 0.f;
        for (int k = 4; k; k >>= 1) v += __shfl_xor_sync(0xffffffffu, v, k);
        if (t == 0) red[0] = v;
    }
    __syncthreads();
    float mu = red[0] * (1.f / H);
    __syncthreads();
    float d = x - mu;
    float q = d * d;
    for (int k = 16; k; k >>= 1) q += __shfl_xor_sync(0xffffffffu, q, k);
    if ((t & 31) == 0) red[t >> 5] = q;
    __syncthreads();
    if (t < 32) {
        float v = (t < 8) ? red[t] : 0.f;
        for (int k = 4; k; k >>= 1) v += __shfl_xor_sync(0xffffffffu, v, k);
        if (t == 0) red[0] = v;
    }
    __syncthreads();
    float var = red[0] * (1.f / H);
    h[o] = d * rsqrtf(var + 1e-5f) * gg[t] + bb[t];
}

// ---------------------------------------------------------------------------
// Multi-head attention for one (b, head, q-chunk of 16 rows).
__global__ __launch_bounds__(256) void attn_kernel(
    const float* __restrict__ q, const float* __restrict__ k,
    const float* __restrict__ v, float* __restrict__ ao)
{
    __shared__ float ks[128 * 65];
    __shared__ float qs[16 * 64];
    __shared__ float ls[16 * 128];
    int qc = blockIdx.x, head = blockIdx.y, b = blockIdx.z;
    int t = threadIdx.x;

    const float* kb = k + b * R * H + head * DH;
    for (int idx = t; idx < 128 * 64; idx += 256) {
        int j = idx >> 6, d = idx & 63;
        ks[j * 65 + d] = kb[j * H + d];
    }
    const float* qb = q + (b * R + qc * 16) * H + head * DH;
    for (int idx = t; idx < 16 * 64; idx += 256) {
        int r = idx >> 6, d = idx & 63;
        qs[r * 64 + d] = qb[r * H + d];
    }
    __syncthreads();

    {   // logits
        int j = t & 127, g = t >> 7;
        float acc[8];
        #pragma unroll
        for (int r = 0; r < 8; r++) acc[r] = 0.f;
        for (int d = 0; d < 64; d++) {
            float kv = ks[j * 65 + d];
            #pragma unroll
            for (int r = 0; r < 8; r++) acc[r] += qs[(g * 8 + r) * 64 + d] * kv;
        }
        #pragma unroll
        for (int r = 0; r < 8; r++) ls[(g * 8 + r) * 128 + j] = acc[r] * 0.125f;
    }
    __syncthreads();

    {   // row softmax
        int qr = t >> 4, jc = t & 15;
        float e[8]; float mx = -3e38f;
        #pragma unroll
        for (int jj = 0; jj < 8; jj++) {
            e[jj] = ls[qr * 128 + jc * 8 + jj];
            mx = fmaxf(mx, e[jj]);
        }
        for (int o = 8; o; o >>= 1) mx = fmaxf(mx, __shfl_xor_sync(0xffffffffu, mx, o));
        float s = 0.f;
        #pragma unroll
        for (int jj = 0; jj < 8; jj++) { e[jj] = expf(e[jj] - mx); s += e[jj]; }
        for (int o = 8; o; o >>= 1) s += __shfl_xor_sync(0xffffffffu, s, o);
        float inv = 1.f / s;
        #pragma unroll
        for (int jj = 0; jj < 8; jj++) ls[qr * 128 + jc * 8 + jj] = e[jj] * inv;
    }
    float* vs = ks;
    const float* vb = v + b * R * H + head * DH;
    for (int idx = t; idx < 128 * 64; idx += 256) {
        int j = idx >> 6, d = idx & 63;
        vs[j * 64 + d] = vb[j * H + d];
    }
    __syncthreads();

    {   // out = P @ V
        int qr = t >> 4, d4 = (t & 15) * 4;
        float4 acc = {0, 0, 0, 0};
        for (int j = 0; j < 128; j++) {
            float p = ls[qr * 128 + j];
            float4 vv = *(const float4*)&vs[j * 64 + d4];
            acc.x += p * vv.x; acc.y += p * vv.y;
            acc.z += p * vv.z; acc.w += p * vv.w;
        }
        *(float4*)&ao[(b * R + qc * 16 + qr) * H + head * DH + d4] = acc;
    }
}

// ---------------------------------------------------------------------------
// abar = mean_r ao; g = abar@Wo + bo; t = relu(g@roW1+rob1); logits; softmax.
__global__ void readout_kernel(const float* __restrict__ ao,
                               const float* __restrict__ Wo, const float* __restrict__ bo,
                               const float* __restrict__ roW1, const float* __restrict__ rob1,
                               const float* __restrict__ roW2, const float* __restrict__ rob2,
                               float* __restrict__ out) {
    __shared__ float s0[H], s1[H];
    __shared__ float red[8];
    int b = blockIdx.x, t = threadIdx.x;
    {
        float s = 0.f;
        const float* ap = ao + b * R * H + t;
        for (int r = 0; r < R; r++) s += ap[r * H];
        s0[t] = s * (1.f / R);
    }
    __syncthreads();
    float acc = bo[t];
    #pragma unroll 8
    for (int k = 0; k < H; k++) acc += s0[k] * Wo[k * H + t];
    s1[t] = acc;
    __syncthreads();
    acc = rob1[t];
    #pragma unroll 8
    for (int k = 0; k < H; k++) acc += s1[k] * roW1[k * H + t];
    __syncthreads();
    s0[t] = fmaxf(acc, 0.f);
    __syncthreads();
    float lg = -3e38f;
    if (t < R) {
        lg = rob2[t];
        #pragma unroll 8
        for (int k = 0; k < H; k++) lg += s0[k] * roW2[k * R + t];
    }
    float m = lg;
    for (int k = 16; k; k >>= 1) m = fmaxf(m, __shfl_xor_sync(0xffffffffu, m, k));
    if ((t & 31) == 0) red[t >> 5] = m;
    __syncthreads();
    if (t < 32) {
        float v = (t < 8) ? red[t] : -3e38f;
        for (int k = 4; k; k >>= 1) v = fmaxf(v, __shfl_xor_sync(0xffffffffu, v, k));
        if (t == 0) red[0] = v;
    }
    __syncthreads();
    float mx = red[0];
    __syncthreads();
    float e = (t < R) ? expf(lg - mx) : 0.f;
    float s = e;
    for (int k = 16; k; k >>= 1) s += __shfl_xor_sync(0xffffffffu, s, k);
    if ((t & 31) == 0) red[t >> 5] = s;
    __syncthreads();
    if (t < 32) {
        float v = (t < 8) ? red[t] : 0.f;
        for (int k = 4; k; k >>= 1) v += __shfl_xor_sync(0xffffffffu, v, k);
        if (t == 0) red[0] = v;
    }
    __syncthreads();
    float sum = red[0];
    if (t < R) out[b * R + t] = e / sum;
}

// ---------------------------------------------------------------------------
static inline GemmJob mkjob(const float* A, const float* W, float* C,
                            const float* bias = nullptr, const float* rowv = nullptr,
                            const float* colv = nullptr, const float* addend = nullptr,
                            int relu = 0) {
    GemmJob j;
    j.A = A; j.W = W; j.bias = bias; j.rowv = rowv; j.colv = colv;
    j.addend = addend; j.C = C; j.relu = relu;
    return j;
}

extern "C" void kernel_launch(void* const* d_in, const int* in_sizes, int n_in,
                              void* d_out, int out_size) {
    const float* x       = (const float*)d_in[0];
    const float* We      = (const float*)d_in[1];
    const float* be      = (const float*)d_in[2];
    const float* msg_W1  = (const float*)d_in[3];
    const float* msg_b1  = (const float*)d_in[4];
    const float* msg_W2  = (const float*)d_in[5];
    const float* msg_b2  = (const float*)d_in[6];
    const float* upd_W1  = (const float*)d_in[7];
    const float* upd_b1  = (const float*)d_in[8];
    const float* upd_W2  = (const float*)d_in[9];
    const float* upd_b2  = (const float*)d_in[10];
    const float* ln_g    = (const float*)d_in[11];
    const float* ln_b    = (const float*)d_in[12];
    const float* rule_adj= (const float*)d_in[13];
    const float* Wq      = (const float*)d_in[14];
    const float* bq      = (const float*)d_in[15];
    const float* Wk      = (const float*)d_in[16];
    const float* bk      = (const float*)d_in[17];
    const float* Wv      = (const float*)d_in[18];
    const float* bv      = (const float*)d_in[19];
    const float* Wo      = (const float*)d_in[20];
    const float* bo      = (const float*)d_in[21];
    const float* roW1    = (const float*)d_in[22];
    const float* rob1    = (const float*)d_in[23];
    const float* roW2    = (const float*)d_in[24];
    const float* rob2    = (const float*)d_in[25];
    float* out = (float*)d_out;

    float* base = nullptr;
    cudaGetSymbolAddress((void**)&base, g_buf);
    float* hb    = base + OFF_H;
    float* aact  = base + OFF_AACT;
    float* bbb   = base + OFF_BB;
    float* aggb  = base + OFF_AGG;
    float* hub   = base + OFF_HU;
    float* upreb = base + OFF_UPRE;
    float* ub    = base + OFF_U;
    float* qb    = base + OFF_Q;
    float* kb    = base + OFF_K;
    float* vb    = base + OFF_V;
    float* aob   = base + OFF_AO;
    float* Ab    = base + OFF_ADJ;
    float* rsb   = base + OFF_RS;
    float* w2ub  = base + OFF_W2U;
    float* c2b   = base + OFF_C2;

    const int M = B * R;  // 1024
    dim3 g3(4, M / 32, 3);      // fused-3 GEMM: 384 CTAs
    dim3 g1(4, M / 32, 1);      // single job: 128 CTAs

    setup_kernel<<<123, 256>>>(rule_adj, Ab, rsb, x, We, be, hb,
                               msg_b2, msg_W2, upd_W1, w2ub, c2b);

    for (int l = 0; l < L; l++) {
        const float* W1a = msg_W1 + l * 2 * HH;
        const float* W1b = W1a + HH;
        // fused: aact = h@W1a ; bb = h@W1b + b1 ; hu = h@Wu1a + b1u + rs*c2
        gemm_tf32_kernel<<<g3, 256>>>(
            mkjob(hb, W1a, aact),
            mkjob(hb, W1b, bbb, msg_b1 + l * H),
            mkjob(hb, upd_W1 + l * 2 * HH, hub, upd_b1 + l * H, rsb, c2b + l * H));
        agg_kernel<<<dim3(4, 4, B), 256>>>(aact, bbb, Ab, aggb);
        // upre = relu(agg@W2u + hu)
        {
            GemmJob j = mkjob(aggb, w2ub + l * HH, upreb, nullptr, nullptr, nullptr, hub, 1);
            gemm_tf32_kernel<<<g1, 256>>>(j, j, j);
        }
        // u = upre@Wu2 + b2u
        {
            GemmJob j = mkjob(upreb, upd_W2 + l * HH, ub, upd_b2 + l * H);
            gemm_tf32_kernel<<<g1, 256>>>(j, j, j);
        }
        ln_kernel<<<M, H>>>(hb, ub, ln_g + l * H, ln_b + l * H);
    }

    // fused q/k/v
    gemm_tf32_kernel<<<g3, 256>>>(
        mkjob(hb, Wq, qb, bq),
        mkjob(hb, Wk, kb, bk),
        mkjob(hb, Wv, vb, bv));
    attn_kernel<<<dim3(R / 16, NH, B), 256>>>(qb, kb, vb, aob);
    readout_kernel<<<B, H>>>(aob, Wo, bo, roW1, rob1, roW2, rob2, out);
    (void)in_sizes; (void)n_in; (void)out_size;
}

// round 11
// speedup vs baseline: 1.0648x; 1.0648x over previous
#include <cuda_runtime.h>
#include <math.h>

// Problem constants
constexpr int B   = 8;
constexpr int R   = 128;
constexpr int H   = 256;
constexpr int IND = 512;
constexpr int L   = 3;
constexpr int NH  = 4;
constexpr int DH  = 64;

constexpr int SZ = B * R * H;  // 262144
constexpr int HH = H * H;

// Scratch layout
constexpr int OFF_H    = 0;
constexpr int OFF_AACT = SZ;
constexpr int OFF_BB   = 2 * SZ;
constexpr int OFF_AGG  = 3 * SZ;
constexpr int OFF_HU   = 4 * SZ;
constexpr int OFF_UPRE = 5 * SZ;
constexpr int OFF_U    = 6 * SZ;
constexpr int OFF_Q    = 7 * SZ;
constexpr int OFF_K    = 8 * SZ;
constexpr int OFF_V    = 9 * SZ;
constexpr int OFF_AO   = 10 * SZ;
constexpr int OFF_ADJ  = 11 * SZ;                 // R*R
constexpr int OFF_RS   = OFF_ADJ + R * R;         // R
constexpr int OFF_W2U  = OFF_RS + R;              // L*H*H
constexpr int OFF_C2   = OFF_W2U + L * HH;        // L*H
constexpr int TOTAL    = OFF_C2 + L * H;

__device__ float g_buf[TOTAL];

typedef unsigned long long u64;

__device__ __forceinline__ u64 pack2(float x) {
    u64 r; asm("mov.b64 %0, {%1, %1};" : "=l"(r) : "f"(x)); return r;
}
__device__ __forceinline__ void fma2(u64& d, u64 a, u64 b) {
    asm("fma.rn.f32x2 %0, %1, %2, %0;" : "+l"(d) : "l"(a), "l"(b));
}
__device__ __forceinline__ float2 unpack2(u64 v) {
    float2 f; asm("mov.b64 {%0, %1}, %2;" : "=f"(f.x), "=f"(f.y) : "l"(v)); return f;
}

struct GemmJob {
    const float* A;
    const float* W;
    const float* bias;    // [256] or null
    const float* rowv;    // [128] or null (indexed m & 127)
    const float* colv;    // [256] (with rowv)
    const float* addend;  // [M,256] or null
    float* C;
    int relu;
};

// ---------------------------------------------------------------------------
// Round-3 proven GEMM tile (256 threads): BM=32, BN=64, BK=32, double-buffered,
// f32x2 accumulation. sh needs 6400 floats.
constexpr int G3_SH = 2 * 32 * 36 + 2 * 32 * 64;  // 6400

__device__ __forceinline__ void g3_tile(const GemmJob& job, int m0, int n0, float* sh) {
    float* AsBuf = sh;             // [2][32*36]
    float* WsBuf = sh + 2 * 32 * 36;

    const float* __restrict__ A = job.A;
    const float* __restrict__ W = job.W;
    const int tid = threadIdx.x;
    const int tx = tid & 15, ty = tid >> 4;

    const int ar = tid >> 3, ac4 = (tid & 7) * 4;
    const int wc0 = tid >> 4, wn0 = (tid & 15) * 4;
    const int wc1 = (tid + 256) >> 4, wn1 = wn0;

    u64 acc[2][2];
    acc[0][0] = acc[0][1] = acc[1][0] = acc[1][1] = 0ull;

    float4 aR = *(const float4*)&A[(m0 + ar) * 256 + ac4];
    float4 wR0 = *(const float4*)&W[wc0 * 256 + n0 + wn0];
    float4 wR1 = *(const float4*)&W[wc1 * 256 + n0 + wn1];
    *(float4*)&AsBuf[ar * 36 + ac4] = aR;
    *(float4*)&WsBuf[wc0 * 64 + wn0] = wR0;
    *(float4*)&WsBuf[wc1 * 64 + wn1] = wR1;
    __syncthreads();

    #pragma unroll 1
    for (int t = 0; t < 8; t++) {
        const int cur = t & 1;
        const bool has_next = (t < 7);
        if (has_next) {
            const int k0 = (t + 1) * 32;
            aR  = *(const float4*)&A[(m0 + ar) * 256 + k0 + ac4];
            wR0 = *(const float4*)&W[(k0 + wc0) * 256 + n0 + wn0];
            wR1 = *(const float4*)&W[(k0 + wc1) * 256 + n0 + wn1];
        }
        const float* __restrict__ as = AsBuf + cur * (32 * 36);
        const float* __restrict__ ws = WsBuf + cur * (32 * 64);
        #pragma unroll
        for (int kk = 0; kk < 32; kk++) {
            ulonglong2 bv = *(const ulonglong2*)&ws[kk * 64 + tx * 4];
            u64 pa0 = pack2(as[(ty * 2 + 0) * 36 + kk]);
            u64 pa1 = pack2(as[(ty * 2 + 1) * 36 + kk]);
            fma2(acc[0][0], pa0, bv.x);
            fma2(acc[0][1], pa0, bv.y);
            fma2(acc[1][0], pa1, bv.x);
            fma2(acc[1][1], pa1, bv.y);
        }
        if (has_next) {
            const int nxt = cur ^ 1;
            *(float4*)&AsBuf[nxt * (32 * 36) + ar * 36 + ac4] = aR;
            *(float4*)&WsBuf[nxt * (32 * 64) + wc0 * 64 + wn0] = wR0;
            *(float4*)&WsBuf[nxt * (32 * 64) + wc1 * 64 + wn1] = wR1;
        }
        __syncthreads();
    }

    const int n = n0 + tx * 4;
    #pragma unroll
    for (int i = 0; i < 2; i++) {
        const int m = m0 + ty * 2 + i;
        float2 p0 = unpack2(acc[i][0]);
        float2 p1 = unpack2(acc[i][1]);
        float4 v = make_float4(p0.x, p0.y, p1.x, p1.y);
        if (job.addend) {
            float4 ad = *(const float4*)&job.addend[m * 256 + n];
            v.x += ad.x; v.y += ad.y; v.z += ad.z; v.w += ad.w;
        }
        if (job.bias) {
            float4 bi = *(const float4*)&job.bias[n];
            v.x += bi.x; v.y += bi.y; v.z += bi.z; v.w += bi.w;
        }
        if (job.rowv) {
            float rv = job.rowv[m & (R - 1)];
            float4 cv = *(const float4*)&job.colv[n];
            v.x += rv * cv.x; v.y += rv * cv.y; v.z += rv * cv.z; v.w += rv * cv.w;
        }
        if (job.relu) {
            v.x = fmaxf(v.x, 0.f); v.y = fmaxf(v.y, 0.f);
            v.z = fmaxf(v.z, 0.f); v.w = fmaxf(v.w, 0.f);
        }
        *(float4*)&job.C[m * 256 + n] = v;
    }
}

__global__ __launch_bounds__(256) void gemm_kernel(GemmJob j0, GemmJob j1, GemmJob j2) {
    __shared__ float sh[G3_SH];
    const GemmJob& job = (blockIdx.z == 0) ? j0 : ((blockIdx.z == 1) ? j1 : j2);
    g3_tile(job, blockIdx.y * 32, blockIdx.x * 64, sh);
}

// ---------------------------------------------------------------------------
// 512-thread GEMM for the 1-CTA/SM launches (upre, u): same BM=32/BN=64/BK=32,
// same accumulation order per output (bit-identical numerics), 1row x 4col per
// thread -> 16 warps/SM at grid 128. Latency hiding doubles.
__global__ __launch_bounds__(512) void gemm512_kernel(GemmJob job) {
    __shared__ float As[2][32 * 33];
    __shared__ float Ws[2][32 * 64];

    const float* __restrict__ A = job.A;
    const float* __restrict__ W = job.W;
    const int m0 = blockIdx.y * 32, n0 = blockIdx.x * 64;
    const int t = threadIdx.x;
    const int tx = t & 15, ty = t >> 4;     // ty: 0..31 (m row), tx: n group
    const int ac2 = tx * 2;                 // A load: 2 floats
    const int wc = tx * 4;                  // W load: float4

    u64 acc0 = 0ull, acc1 = 0ull;

    const float* Aptr = A + (m0 + ty) * 256 + ac2;
    const float* Wptr = W + ty * 256 + n0 + wc;

    float2 aR = *(const float2*)Aptr;
    float4 wR = *(const float4*)Wptr;
    As[0][(ac2 + 0) * 33 + ty] = aR.x;
    As[0][(ac2 + 1) * 33 + ty] = aR.y;
    *(float4*)&Ws[0][ty * 64 + wc] = wR;
    __syncthreads();

    #pragma unroll 1
    for (int kt = 0; kt < 8; kt++) {
        const int cur = kt & 1;
        if (kt < 7) {
            aR = *(const float2*)(Aptr + (kt + 1) * 32);
            wR = *(const float4*)(Wptr + (kt + 1) * 32 * 256);
        }
        const float* __restrict__ as = As[cur];
        const float* __restrict__ ws = Ws[cur];
        #pragma unroll
        for (int kk = 0; kk < 32; kk++) {
            ulonglong2 bv = *(const ulonglong2*)&ws[kk * 64 + wc];
            u64 pa = pack2(as[kk * 33 + ty]);
            fma2(acc0, pa, bv.x);
            fma2(acc1, pa, bv.y);
        }
        if (kt < 7) {
            const int nxt = cur ^ 1;
            As[nxt][(ac2 + 0) * 33 + ty] = aR.x;
            As[nxt][(ac2 + 1) * 33 + ty] = aR.y;
            *(float4*)&Ws[nxt][ty * 64 + wc] = wR;
        }
        __syncthreads();
    }

    const int m = m0 + ty;
    const int n = n0 + wc;
    float2 p0 = unpack2(acc0);
    float2 p1 = unpack2(acc1);
    float4 v = make_float4(p0.x, p0.y, p1.x, p1.y);
    if (job.addend) {
        float4 ad = *(const float4*)&job.addend[m * 256 + n];
        v.x += ad.x; v.y += ad.y; v.z += ad.z; v.w += ad.w;
    }
    if (job.bias) {
        float4 bi = *(const float4*)&job.bias[n];
        v.x += bi.x; v.y += bi.y; v.z += bi.z; v.w += bi.w;
    }
    if (job.rowv) {
        float rv = job.rowv[m & (R - 1)];
        float4 cv = *(const float4*)&job.colv[n];
        v.x += rv * cv.x; v.y += rv * cv.y; v.z += rv * cv.z; v.w += rv * cv.w;
    }
    if (job.relu) {
        v.x = fmaxf(v.x, 0.f); v.y = fmaxf(v.y, 0.f);
        v.z = fmaxf(v.z, 0.f); v.w = fmaxf(v.w, 0.f);
    }
    *(float4*)&job.C[m * 256 + n] = v;
}

// ---------------------------------------------------------------------------
// Setup: 0..95 -> W2u tiles ; 96..111 -> prep_A ; 112..119 -> h0 ; 120..122 -> c2
__global__ __launch_bounds__(256) void setup_kernel(
    const float* __restrict__ rule_adj, float* __restrict__ A, float* __restrict__ rowsum,
    const float* __restrict__ x, const float* __restrict__ We,
    const float* __restrict__ be, float* __restrict__ h,
    const float* __restrict__ msg_b2, const float* __restrict__ msg_W2,
    const float* __restrict__ upd_W1, float* __restrict__ w2u, float* __restrict__ c2)
{
    __shared__ float sh[G3_SH];
    int bid = blockIdx.x, t = threadIdx.x;
    if (bid < 96) {
        int l = bid >> 5, rem = bid & 31;
        GemmJob j;
        j.A = msg_W2 + l * HH; j.W = upd_W1 + l * 2 * HH + HH;
        j.bias = nullptr; j.rowv = nullptr; j.colv = nullptr; j.addend = nullptr;
        j.C = w2u + l * HH; j.relu = 0;
        g3_tile(j, (rem >> 2) * 32, (rem & 3) * 64, sh);
    } else if (bid < 112) {
        int wid = t >> 5, lane = t & 31;
        int i = (bid - 96) * 8 + wid;
        float4 va = *(const float4*)&rule_adj[i * R + lane * 4];
        float s0 = 1.f / (1.f + expf(-va.x));
        float s1 = 1.f / (1.f + expf(-va.y));
        float s2 = 1.f / (1.f + expf(-va.z));
        float s3 = 1.f / (1.f + expf(-va.w));
        int c = lane * 4;
        if (i == c + 0) s0 = 0.f;
        if (i == c + 1) s1 = 0.f;
        if (i == c + 2) s2 = 0.f;
        if (i == c + 3) s3 = 0.f;
        *(float4*)&A[i * R + c] = make_float4(s0, s1, s2, s3);
        float part = s0 + s1 + s2 + s3;
        for (int o = 16; o; o >>= 1) part += __shfl_xor_sync(0xffffffffu, part, o);
        if (lane == 0) rowsum[i] = part;
    } else if (bid < 120) {
        int b = bid - 112;
        float* xs = sh;
        xs[t]       = x[b * IND + t];
        xs[t + 256] = x[b * IND + 256 + t];
        __syncthreads();
        float acc = be[t];
        #pragma unroll 8
        for (int k = 0; k < IND; k++) acc += xs[k] * We[k * H + t];
        for (int r = 0; r < R; r++) h[(b * R + r) * H + t] = acc;
    } else {
        int l = bid - 120;
        float* bs = sh;
        bs[t] = msg_b2[l * H + t];
        __syncthreads();
        const float* W = upd_W1 + l * 2 * HH + HH;
        float acc = 0.f;
        #pragma unroll 8
        for (int k = 0; k < H; k++) acc += bs[k] * W[k * H + t];
        c2[l * H + t] = acc;
    }
}

// ---------------------------------------------------------------------------
// aggpre[b,i,h] = sum_j A[i,j] * relu(a[b,i,h] + bb[b,j,h])   (b1 folded into bb)
__global__ __launch_bounds__(256) void agg_kernel(
    const float* __restrict__ a, const float* __restrict__ bbg,
    const float* __restrict__ A, float* __restrict__ out)
{
    __shared__ float bbs[128 * 64];
    int hc = blockIdx.x * 64, ic = blockIdx.y * 32, b = blockIdx.z;
    int t = threadIdx.x;
    const float* bp = bbg + b * R * H;
    for (int idx = t; idx < 2048; idx += 256) {
        int j = idx >> 4, c4 = (idx & 15) * 4;
        *(float4*)&bbs[j * 64 + c4] = *(const float4*)&bp[j * H + hc + c4];
    }
    __syncthreads();
    int hl = (t & 15) * 4;
    int i0 = ic + (t >> 4) * 2;
    float4 av0 = *(const float4*)&a[(b * R + i0) * H + hc + hl];
    float4 av1 = *(const float4*)&a[(b * R + i0 + 1) * H + hc + hl];
    float4 ac0 = {0, 0, 0, 0}, ac1 = {0, 0, 0, 0};
    const float* Ar = A + i0 * R;
    #pragma unroll 4
    for (int j = 0; j < R; j++) {
        float4 bv = *(const float4*)&bbs[j * 64 + hl];
        float w0 = __ldg(&Ar[j]);
        float w1 = __ldg(&Ar[R + j]);
        ac0.x += w0 * fmaxf(av0.x + bv.x, 0.f);
        ac0.y += w0 * fmaxf(av0.y + bv.y, 0.f);
        ac0.z += w0 * fmaxf(av0.z + bv.z, 0.f);
        ac0.w += w0 * fmaxf(av0.w + bv.w, 0.f);
        ac1.x += w1 * fmaxf(av1.x + bv.x, 0.f);
        ac1.y += w1 * fmaxf(av1.y + bv.y, 0.f);
        ac1.z += w1 * fmaxf(av1.z + bv.z, 0.f);
        ac1.w += w1 * fmaxf(av1.w + bv.w, 0.f);
    }
    *(float4*)&out[(b * R + i0) * H + hc + hl]     = ac0;
    *(float4*)&out[(b * R + i0 + 1) * H + hc + hl] = ac1;
}

// ---------------------------------------------------------------------------
// h = LayerNorm(h + u) * g + beta
__global__ void ln_kernel(float* __restrict__ h, const float* __restrict__ u,
                          const float* __restrict__ gg, const float* __restrict__ bb) {
    __shared__ float red[8];
    int row = blockIdx.x, t = threadIdx.x;
    int o = row * H + t;
    float x = h[o] + u[o];
    float s = x;
    for (int k = 16; k; k >>= 1) s += __shfl_xor_sync(0xffffffffu, s, k);
    if ((t & 31) == 0) red[t >> 5] = s;
    __syncthreads();
    if (t < 32) {
        float v = (t < 8) ? red[t] : 0.f;
        for (int k = 4; k; k >>= 1) v += __shfl_xor_sync(0xffffffffu, v, k);
        if (t == 0) red[0] = v;
    }
    __syncthreads();
    float mu = red[0] * (1.f / H);
    __syncthreads();
    float d = x - mu;
    float q = d * d;
    for (int k = 16; k; k >>= 1) q += __shfl_xor_sync(0xffffffffu, q, k);
    if ((t & 31) == 0) red[t >> 5] = q;
    __syncthreads();
    if (t < 32) {
        float v = (t < 8) ? red[t] : 0.f;
        for (int k = 4; k; k >>= 1) v += __shfl_xor_sync(0xffffffffu, v, k);
        if (t == 0) red[0] = v;
    }
    __syncthreads();
    float var = red[0] * (1.f / H);
    h[o] = d * rsqrtf(var + 1e-5f) * gg[t] + bb[t];
}

// ---------------------------------------------------------------------------
// Multi-head attention for one (b, head, q-chunk of 16 rows).
__global__ __launch_bounds__(256) void attn_kernel(
    const float* __restrict__ q, const float* __restrict__ k,
    const float* __restrict__ v, float* __restrict__ ao)
{
    __shared__ float ks[128 * 65];
    __shared__ float qs[16 * 64];
    __shared__ float ls[16 * 128];
    int qc = blockIdx.x, head = blockIdx.y, b = blockIdx.z;
    int t = threadIdx.x;

    const float* kb = k + b * R * H + head * DH;
    for (int idx = t; idx < 128 * 64; idx += 256) {
        int j = idx >> 6, d = idx & 63;
        ks[j * 65 + d] = kb[j * H + d];
    }
    const float* qb = q + (b * R + qc * 16) * H + head * DH;
    for (int idx = t; idx < 16 * 64; idx += 256) {
        int r = idx >> 6, d = idx & 63;
        qs[r * 64 + d] = qb[r * H + d];
    }
    __syncthreads();

    {   // logits
        int j = t & 127, g = t >> 7;
        float acc[8];
        #pragma unroll
        for (int r = 0; r < 8; r++) acc[r] = 0.f;
        for (int d = 0; d < 64; d++) {
            float kv = ks[j * 65 + d];
            #pragma unroll
            for (int r = 0; r < 8; r++) acc[r] += qs[(g * 8 + r) * 64 + d] * kv;
        }
        #pragma unroll
        for (int r = 0; r < 8; r++) ls[(g * 8 + r) * 128 + j] = acc[r] * 0.125f;
    }
    __syncthreads();

    {   // row softmax
        int qr = t >> 4, jc = t & 15;
        float e[8]; float mx = -3e38f;
        #pragma unroll
        for (int jj = 0; jj < 8; jj++) {
            e[jj] = ls[qr * 128 + jc * 8 + jj];
            mx = fmaxf(mx, e[jj]);
        }
        for (int o = 8; o; o >>= 1) mx = fmaxf(mx, __shfl_xor_sync(0xffffffffu, mx, o));
        float s = 0.f;
        #pragma unroll
        for (int jj = 0; jj < 8; jj++) { e[jj] = expf(e[jj] - mx); s += e[jj]; }
        for (int o = 8; o; o >>= 1) s += __shfl_xor_sync(0xffffffffu, s, o);
        float inv = 1.f / s;
        #pragma unroll
        for (int jj = 0; jj < 8; jj++) ls[qr * 128 + jc * 8 + jj] = e[jj] * inv;
    }
    float* vs = ks;
    const float* vb = v + b * R * H + head * DH;
    for (int idx = t; idx < 128 * 64; idx += 256) {
        int j = idx >> 6, d = idx & 63;
        vs[j * 64 + d] = vb[j * H + d];
    }
    __syncthreads();

    {   // out = P @ V
        int qr = t >> 4, d4 = (t & 15) * 4;
        float4 acc = {0, 0, 0, 0};
        for (int j = 0; j < 128; j++) {
            float p = ls[qr * 128 + j];
            float4 vv = *(const float4*)&vs[j * 64 + d4];
            acc.x += p * vv.x; acc.y += p * vv.y;
            acc.z += p * vv.z; acc.w += p * vv.w;
        }
        *(float4*)&ao[(b * R + qc * 16 + qr) * H + head * DH + d4] = acc;
    }
}

// ---------------------------------------------------------------------------
// abar = mean_r ao; g = abar@Wo + bo; t = relu(g@roW1+rob1); logits; softmax.
__global__ void readout_kernel(const float* __restrict__ ao,
                               const float* __restrict__ Wo, const float* __restrict__ bo,
                               const float* __restrict__ roW1, const float* __restrict__ rob1,
                               const float* __restrict__ roW2, const float* __restrict__ rob2,
                               float* __restrict__ out) {
    __shared__ float s0[H], s1[H];
    __shared__ float red[8];
    int b = blockIdx.x, t = threadIdx.x;
    {
        float s = 0.f;
        const float* ap = ao + b * R * H + t;
        for (int r = 0; r < R; r++) s += ap[r * H];
        s0[t] = s * (1.f / R);
    }
    __syncthreads();
    float acc = bo[t];
    #pragma unroll 8
    for (int k = 0; k < H; k++) acc += s0[k] * Wo[k * H + t];
    s1[t] = acc;
    __syncthreads();
    acc = rob1[t];
    #pragma unroll 8
    for (int k = 0; k < H; k++) acc += s1[k] * roW1[k * H + t];
    __syncthreads();
    s0[t] = fmaxf(acc, 0.f);
    __syncthreads();
    float lg = -3e38f;
    if (t < R) {
        lg = rob2[t];
        #pragma unroll 8
        for (int k = 0; k < H; k++) lg += s0[k] * roW2[k * R + t];
    }
    float m = lg;
    for (int k = 16; k; k >>= 1) m = fmaxf(m, __shfl_xor_sync(0xffffffffu, m, k));
    if ((t & 31) == 0) red[t >> 5] = m;
    __syncthreads();
    if (t < 32) {
        float v = (t < 8) ? red[t] : -3e38f;
        for (int k = 4; k; k >>= 1) v = fmaxf(v, __shfl_xor_sync(0xffffffffu, v, k));
        if (t == 0) red[0] = v;
    }
    __syncthreads();
    float mx = red[0];
    __syncthreads();
    float e = (t < R) ? expf(lg - mx) : 0.f;
    float s = e;
    for (int k = 16; k; k >>= 1) s += __shfl_xor_sync(0xffffffffu, s, k);
    if ((t & 31) == 0) red[t >> 5] = s;
    __syncthreads();
    if (t < 32) {
        float v = (t < 8) ? red[t] : 0.f;
        for (int k = 4; k; k >>= 1) v += __shfl_xor_sync(0xffffffffu, v, k);
        if (t == 0) red[0] = v;
    }
    __syncthreads();
    float sum = red[0];
    if (t < R) out[b * R + t] = e / sum;
}

// ---------------------------------------------------------------------------
static inline GemmJob mkjob(const float* A, const float* W, float* C,
                            const float* bias = nullptr, const float* rowv = nullptr,
                            const float* colv = nullptr, const float* addend = nullptr,
                            int relu = 0) {
    GemmJob j;
    j.A = A; j.W = W; j.bias = bias; j.rowv = rowv; j.colv = colv;
    j.addend = addend; j.C = C; j.relu = relu;
    return j;
}

extern "C" void kernel_launch(void* const* d_in, const int* in_sizes, int n_in,
                              void* d_out, int out_size) {
    const float* x       = (const float*)d_in[0];
    const float* We      = (const float*)d_in[1];
    const float* be      = (const float*)d_in[2];
    const float* msg_W1  = (const float*)d_in[3];
    const float* msg_b1  = (const float*)d_in[4];
    const float* msg_W2  = (const float*)d_in[5];
    const float* msg_b2  = (const float*)d_in[6];
    const float* upd_W1  = (const float*)d_in[7];
    const float* upd_b1  = (const float*)d_in[8];
    const float* upd_W2  = (const float*)d_in[9];
    const float* upd_b2  = (const float*)d_in[10];
    const float* ln_g    = (const float*)d_in[11];
    const float* ln_b    = (const float*)d_in[12];
    const float* rule_adj= (const float*)d_in[13];
    const float* Wq      = (const float*)d_in[14];
    const float* bq      = (const float*)d_in[15];
    const float* Wk      = (const float*)d_in[16];
    const float* bk      = (const float*)d_in[17];
    const float* Wv      = (const float*)d_in[18];
    const float* bv      = (const float*)d_in[19];
    const float* Wo      = (const float*)d_in[20];
    const float* bo      = (const float*)d_in[21];
    const float* roW1    = (const float*)d_in[22];
    const float* rob1    = (const float*)d_in[23];
    const float* roW2    = (const float*)d_in[24];
    const float* rob2    = (const float*)d_in[25];
    float* out = (float*)d_out;

    float* base = nullptr;
    cudaGetSymbolAddress((void**)&base, g_buf);
    float* hb    = base + OFF_H;
    float* aact  = base + OFF_AACT;
    float* bbb   = base + OFF_BB;
    float* aggb  = base + OFF_AGG;
    float* hub   = base + OFF_HU;
    float* upreb = base + OFF_UPRE;
    float* ub    = base + OFF_U;
    float* qb    = base + OFF_Q;
    float* kb    = base + OFF_K;
    float* vb    = base + OFF_V;
    float* aob   = base + OFF_AO;
    float* Ab    = base + OFF_ADJ;
    float* rsb   = base + OFF_RS;
    float* w2ub  = base + OFF_W2U;
    float* c2b   = base + OFF_C2;

    const int M = B * R;  // 1024
    dim3 g3(4, M / 32, 3);      // fused-3 GEMM: 384 CTAs
    dim3 g512(4, M / 32);       // 512-thread GEMM: 128 CTAs

    setup_kernel<<<123, 256>>>(rule_adj, Ab, rsb, x, We, be, hb,
                               msg_b2, msg_W2, upd_W1, w2ub, c2b);

    for (int l = 0; l < L; l++) {
        const float* W1a = msg_W1 + l * 2 * HH;
        const float* W1b = W1a + HH;
        // fused: aact = h@W1a ; bb = h@W1b + b1 ; hu = h@Wu1a + b1u + rs*c2
        gemm_kernel<<<g3, 256>>>(
            mkjob(hb, W1a, aact),
            mkjob(hb, W1b, bbb, msg_b1 + l * H),
            mkjob(hb, upd_W1 + l * 2 * HH, hub, upd_b1 + l * H, rsb, c2b + l * H));
        agg_kernel<<<dim3(4, 4, B), 256>>>(aact, bbb, Ab, aggb);
        // upre = relu(agg@W2u + hu)
        gemm512_kernel<<<g512, 512>>>(
            mkjob(aggb, w2ub + l * HH, upreb, nullptr, nullptr, nullptr, hub, 1));
        // u = upre@Wu2 + b2u
        gemm512_kernel<<<g512, 512>>>(
            mkjob(upreb, upd_W2 + l * HH, ub, upd_b2 + l * H));
        ln_kernel<<<M, H>>>(hb, ub, ln_g + l * H, ln_b + l * H);
    }

    // fused q/k/v
    gemm_kernel<<<g3, 256>>>(
        mkjob(hb, Wq, qb, bq),
        mkjob(hb, Wk, kb, bk),
        mkjob(hb, Wv, vb, bv));
    attn_kernel<<<dim3(R / 16, NH, B), 256>>>(qb, kb, vb, aob);
    readout_kernel<<<B, H>>>(aob, Wo, bo, roW1, rob1, roW2, rob2, out);
    (void)in_sizes; (void)n_in; (void)out_size;
}

// round 13
// speedup vs baseline: 1.2506x; 1.1745x over previous
#include <cuda_runtime.h>
#include <math.h>

// Problem constants
constexpr int B   = 8;
constexpr int R   = 128;
constexpr int H   = 256;
constexpr int IND = 512;
constexpr int L   = 3;
constexpr int NH  = 4;
constexpr int DH  = 64;

constexpr int SZ = B * R * H;  // 262144
constexpr int HH = H * H;

// Scratch layout
constexpr int OFF_H    = 0;
constexpr int OFF_AACT = SZ;
constexpr int OFF_BB   = 2 * SZ;
constexpr int OFF_AGG  = 3 * SZ;
constexpr int OFF_HU   = 4 * SZ;
constexpr int OFF_UPRE = 5 * SZ;
constexpr int OFF_U    = 6 * SZ;
constexpr int OFF_Q    = 7 * SZ;
constexpr int OFF_K    = 8 * SZ;
constexpr int OFF_V    = 9 * SZ;
constexpr int OFF_AO   = 10 * SZ;
constexpr int OFF_ADJ  = 11 * SZ;                 // R*R
constexpr int OFF_RS   = OFF_ADJ + R * R;         // R
constexpr int OFF_W2U  = OFF_RS + R;              // L*H*H
constexpr int OFF_C2   = OFF_W2U + L * HH;        // L*H
constexpr int TOTAL    = OFF_C2 + L * H;

__device__ float g_buf[TOTAL];

typedef unsigned long long u64;

__device__ __forceinline__ u64 pack2(float x) {
    u64 r; asm("mov.b64 %0, {%1, %1};" : "=l"(r) : "f"(x)); return r;
}
__device__ __forceinline__ void fma2(u64& d, u64 a, u64 b) {
    asm("fma.rn.f32x2 %0, %1, %2, %0;" : "+l"(d) : "l"(a), "l"(b));
}
__device__ __forceinline__ float2 unpack2(u64 v) {
    float2 f; asm("mov.b64 {%0, %1}, %2;" : "=f"(f.x), "=f"(f.y) : "l"(v)); return f;
}

struct GemmJob {
    const float* A;
    const float* W;
    const float* bias;    // [256] or null
    const float* rowv;    // [128] or null (indexed m & 127)
    const float* colv;    // [256] (with rowv)
    const float* addend;  // [M,256] or null
    float* C;
    int relu;
};

// ---------------------------------------------------------------------------
// Round-3 proven GEMM tile (256 threads): BM=32, BN=64, BK=32, double-buffered,
// f32x2 accumulation. sh needs 6400 floats. Used for upre/u (128-CTA grids)
// and the W2u tiles inside setup.
constexpr int G3_SH = 2 * 32 * 36 + 2 * 32 * 64;  // 6400

__device__ __forceinline__ void g3_tile(const GemmJob& job, int m0, int n0, float* sh) {
    float* AsBuf = sh;             // [2][32*36]
    float* WsBuf = sh + 2 * 32 * 36;

    const float* __restrict__ A = job.A;
    const float* __restrict__ W = job.W;
    const int tid = threadIdx.x;
    const int tx = tid & 15, ty = tid >> 4;

    const int ar = tid >> 3, ac4 = (tid & 7) * 4;
    const int wc0 = tid >> 4, wn0 = (tid & 15) * 4;
    const int wc1 = (tid + 256) >> 4, wn1 = wn0;

    u64 acc[2][2];
    acc[0][0] = acc[0][1] = acc[1][0] = acc[1][1] = 0ull;

    float4 aR = *(const float4*)&A[(m0 + ar) * 256 + ac4];
    float4 wR0 = *(const float4*)&W[wc0 * 256 + n0 + wn0];
    float4 wR1 = *(const float4*)&W[wc1 * 256 + n0 + wn1];
    *(float4*)&AsBuf[ar * 36 + ac4] = aR;
    *(float4*)&WsBuf[wc0 * 64 + wn0] = wR0;
    *(float4*)&WsBuf[wc1 * 64 + wn1] = wR1;
    __syncthreads();

    #pragma unroll 1
    for (int t = 0; t < 8; t++) {
        const int cur = t & 1;
        const bool has_next = (t < 7);
        if (has_next) {
            const int k0 = (t + 1) * 32;
            aR  = *(const float4*)&A[(m0 + ar) * 256 + k0 + ac4];
            wR0 = *(const float4*)&W[(k0 + wc0) * 256 + n0 + wn0];
            wR1 = *(const float4*)&W[(k0 + wc1) * 256 + n0 + wn1];
        }
        const float* __restrict__ as = AsBuf + cur * (32 * 36);
        const float* __restrict__ ws = WsBuf + cur * (32 * 64);
        #pragma unroll
        for (int kk = 0; kk < 32; kk++) {
            ulonglong2 bv = *(const ulonglong2*)&ws[kk * 64 + tx * 4];
            u64 pa0 = pack2(as[(ty * 2 + 0) * 36 + kk]);
            u64 pa1 = pack2(as[(ty * 2 + 1) * 36 + kk]);
            fma2(acc[0][0], pa0, bv.x);
            fma2(acc[0][1], pa0, bv.y);
            fma2(acc[1][0], pa1, bv.x);
            fma2(acc[1][1], pa1, bv.y);
        }
        if (has_next) {
            const int nxt = cur ^ 1;
            *(float4*)&AsBuf[nxt * (32 * 36) + ar * 36 + ac4] = aR;
            *(float4*)&WsBuf[nxt * (32 * 64) + wc0 * 64 + wn0] = wR0;
            *(float4*)&WsBuf[nxt * (32 * 64) + wc1 * 64 + wn1] = wR1;
        }
        __syncthreads();
    }

    const int n = n0 + tx * 4;
    #pragma unroll
    for (int i = 0; i < 2; i++) {
        const int m = m0 + ty * 2 + i;
        float2 p0 = unpack2(acc[i][0]);
        float2 p1 = unpack2(acc[i][1]);
        float4 v = make_float4(p0.x, p0.y, p1.x, p1.y);
        if (job.addend) {
            float4 ad = *(const float4*)&job.addend[m * 256 + n];
            v.x += ad.x; v.y += ad.y; v.z += ad.z; v.w += ad.w;
        }
        if (job.bias) {
            float4 bi = *(const float4*)&job.bias[n];
            v.x += bi.x; v.y += bi.y; v.z += bi.z; v.w += bi.w;
        }
        if (job.rowv) {
            float rv = job.rowv[m & (R - 1)];
            float4 cv = *(const float4*)&job.colv[n];
            v.x += rv * cv.x; v.y += rv * cv.y; v.z += rv * cv.z; v.w += rv * cv.w;
        }
        if (job.relu) {
            v.x = fmaxf(v.x, 0.f); v.y = fmaxf(v.y, 0.f);
            v.z = fmaxf(v.z, 0.f); v.w = fmaxf(v.w, 0.f);
        }
        *(float4*)&job.C[m * 256 + n] = v;
    }
}

__global__ __launch_bounds__(256) void gemm1_kernel(GemmJob job) {
    __shared__ float sh[G3_SH];
    g3_tile(job, blockIdx.y * 32, blockIdx.x * 64, sh);
}

// ---------------------------------------------------------------------------
// Wide fused GEMM: BM=64, BN=64, BK=32, 256 threads, 4 rows x 4 cols per
// thread. Per kk: 1 float4 A read + 1 ulonglong2 W read -> 8 FFMA2:
// compute-bound (LDS bytes per output halved vs the 2x4 tile).
// Up to 3 independent jobs via blockIdx.z.
__global__ __launch_bounds__(256) void gemm44_kernel(GemmJob j0, GemmJob j1, GemmJob j2) {
    __shared__ float As[2][32][68];   // [buf][k][m]
    __shared__ float Ws[2][32][64];   // [buf][k][n]

    const GemmJob& job = (blockIdx.z == 0) ? j0 : ((blockIdx.z == 1) ? j1 : j2);
    const float* __restrict__ A = job.A;
    const float* __restrict__ W = job.W;
    const int m0 = blockIdx.y * 64, n0 = blockIdx.x * 64;
    const int t = threadIdx.x;
    const int tx = t & 15, ty = t >> 4;          // compute: n = tx*4, m = ty*4
    const int ar = t >> 2, ac8 = (t & 3) * 8;    // A load: row, k-octet
    const int wr = t >> 4, wc = (t & 15) * 4;    // W load

    u64 acc[4][2];
    #pragma unroll
    for (int r = 0; r < 4; r++) { acc[r][0] = 0ull; acc[r][1] = 0ull; }

    const float* Aptr = A + (m0 + ar) * 256 + ac8;
    const float* Wptr = W + wr * 256 + n0 + wc;

    float4 aR0 = *(const float4*)Aptr;
    float4 aR1 = *(const float4*)(Aptr + 4);
    float4 wR0 = *(const float4*)Wptr;
    float4 wR1 = *(const float4*)(Wptr + 16 * 256);
    {
        As[0][ac8 + 0][ar] = aR0.x; As[0][ac8 + 1][ar] = aR0.y;
        As[0][ac8 + 2][ar] = aR0.z; As[0][ac8 + 3][ar] = aR0.w;
        As[0][ac8 + 4][ar] = aR1.x; As[0][ac8 + 5][ar] = aR1.y;
        As[0][ac8 + 6][ar] = aR1.z; As[0][ac8 + 7][ar] = aR1.w;
        *(float4*)&Ws[0][wr][wc] = wR0;
        *(float4*)&Ws[0][wr + 16][wc] = wR1;
    }
    __syncthreads();

    #pragma unroll 1
    for (int kt = 0; kt < 8; kt++) {
        const int cur = kt & 1;
        if (kt < 7) {
            const int k0 = (kt + 1) * 32;
            aR0 = *(const float4*)(Aptr + k0);
            aR1 = *(const float4*)(Aptr + k0 + 4);
            wR0 = *(const float4*)(Wptr + k0 * 256);
            wR1 = *(const float4*)(Wptr + (k0 + 16) * 256);
        }
        #pragma unroll
        for (int kk = 0; kk < 32; kk++) {
            float4 av = *(const float4*)&As[cur][kk][ty * 4];
            ulonglong2 wv = *(const ulonglong2*)&Ws[cur][kk][tx * 4];
            u64 p0 = pack2(av.x), p1 = pack2(av.y), p2 = pack2(av.z), p3 = pack2(av.w);
            fma2(acc[0][0], p0, wv.x); fma2(acc[0][1], p0, wv.y);
            fma2(acc[1][0], p1, wv.x); fma2(acc[1][1], p1, wv.y);
            fma2(acc[2][0], p2, wv.x); fma2(acc[2][1], p2, wv.y);
            fma2(acc[3][0], p3, wv.x); fma2(acc[3][1], p3, wv.y);
        }
        if (kt < 7) {
            const int nxt = cur ^ 1;
            As[nxt][ac8 + 0][ar] = aR0.x; As[nxt][ac8 + 1][ar] = aR0.y;
            As[nxt][ac8 + 2][ar] = aR0.z; As[nxt][ac8 + 3][ar] = aR0.w;
            As[nxt][ac8 + 4][ar] = aR1.x; As[nxt][ac8 + 5][ar] = aR1.y;
            As[nxt][ac8 + 6][ar] = aR1.z; As[nxt][ac8 + 7][ar] = aR1.w;
            *(float4*)&Ws[nxt][wr][wc] = wR0;
            *(float4*)&Ws[nxt][wr + 16][wc] = wR1;
        }
        __syncthreads();
    }

    const int n = n0 + tx * 4;
    float4 bi, cv;
    if (job.bias) bi = *(const float4*)&job.bias[n];
    if (job.rowv) cv = *(const float4*)&job.colv[n];
    #pragma unroll
    for (int r = 0; r < 4; r++) {
        const int m = m0 + ty * 4 + r;
        float2 p0 = unpack2(acc[r][0]);
        float2 p1 = unpack2(acc[r][1]);
        float4 v = make_float4(p0.x, p0.y, p1.x, p1.y);
        if (job.addend) {
            float4 ad = *(const float4*)&job.addend[m * 256 + n];
            v.x += ad.x; v.y += ad.y; v.z += ad.z; v.w += ad.w;
        }
        if (job.bias) {
            v.x += bi.x; v.y += bi.y; v.z += bi.z; v.w += bi.w;
        }
        if (job.rowv) {
            float rv = job.rowv[m & (R - 1)];
            v.x += rv * cv.x; v.y += rv * cv.y; v.z += rv * cv.z; v.w += rv * cv.w;
        }
        if (job.relu) {
            v.x = fmaxf(v.x, 0.f); v.y = fmaxf(v.y, 0.f);
            v.z = fmaxf(v.z, 0.f); v.w = fmaxf(v.w, 0.f);
        }
        *(float4*)&job.C[m * 256 + n] = v;
    }
}

// ---------------------------------------------------------------------------
// Setup: 0..95 -> W2u tiles ; 96..111 -> prep_A ; 112..119 -> h0 ; 120..122 -> c2
__global__ __launch_bounds__(256) void setup_kernel(
    const float* __restrict__ rule_adj, float* __restrict__ A, float* __restrict__ rowsum,
    const float* __restrict__ x, const float* __restrict__ We,
    const float* __restrict__ be, float* __restrict__ h,
    const float* __restrict__ msg_b2, const float* __restrict__ msg_W2,
    const float* __restrict__ upd_W1, float* __restrict__ w2u, float* __restrict__ c2)
{
    __shared__ float sh[G3_SH];
    int bid = blockIdx.x, t = threadIdx.x;
    if (bid < 96) {
        int l = bid >> 5, rem = bid & 31;
        GemmJob j;
        j.A = msg_W2 + l * HH; j.W = upd_W1 + l * 2 * HH + HH;
        j.bias = nullptr; j.rowv = nullptr; j.colv = nullptr; j.addend = nullptr;
        j.C = w2u + l * HH; j.relu = 0;
        g3_tile(j, (rem >> 2) * 32, (rem & 3) * 64, sh);
    } else if (bid < 112) {
        int wid = t >> 5, lane = t & 31;
        int i = (bid - 96) * 8 + wid;
        float4 va = *(const float4*)&rule_adj[i * R + lane * 4];
        float s0 = 1.f / (1.f + expf(-va.x));
        float s1 = 1.f / (1.f + expf(-va.y));
        float s2 = 1.f / (1.f + expf(-va.z));
        float s3 = 1.f / (1.f + expf(-va.w));
        int c = lane * 4;
        if (i == c + 0) s0 = 0.f;
        if (i == c + 1) s1 = 0.f;
        if (i == c + 2) s2 = 0.f;
        if (i == c + 3) s3 = 0.f;
        *(float4*)&A[i * R + c] = make_float4(s0, s1, s2, s3);
        float part = s0 + s1 + s2 + s3;
        for (int o = 16; o; o >>= 1) part += __shfl_xor_sync(0xffffffffu, part, o);
        if (lane == 0) rowsum[i] = part;
    } else if (bid < 120) {
        int b = bid - 112;
        float* xs = sh;
        xs[t]       = x[b * IND + t];
        xs[t + 256] = x[b * IND + 256 + t];
        __syncthreads();
        float acc = be[t];
        #pragma unroll 8
        for (int k = 0; k < IND; k++) acc += xs[k] * We[k * H + t];
        for (int r = 0; r < R; r++) h[(b * R + r) * H + t] = acc;
    } else {
        int l = bid - 120;
        float* bs = sh;
        bs[t] = msg_b2[l * H + t];
        __syncthreads();
        const float* W = upd_W1 + l * 2 * HH + HH;
        float acc = 0.f;
        #pragma unroll 8
        for (int k = 0; k < H; k++) acc += bs[k] * W[k * H + t];
        c2[l * H + t] = acc;
    }
}

// ---------------------------------------------------------------------------
// aggpre[b,i,h] = sum_j A[i,j] * relu(a[b,i,h] + bb[b,j,h])   (b1 folded into bb)
__global__ __launch_bounds__(256) void agg_kernel(
    const float* __restrict__ a, const float* __restrict__ bbg,
    const float* __restrict__ A, float* __restrict__ out)
{
    __shared__ float bbs[128 * 64];
    int hc = blockIdx.x * 64, ic = blockIdx.y * 32, b = blockIdx.z;
    int t = threadIdx.x;
    const float* bp = bbg + b * R * H;
    for (int idx = t; idx < 2048; idx += 256) {
        int j = idx >> 4, c4 = (idx & 15) * 4;
        *(float4*)&bbs[j * 64 + c4] = *(const float4*)&bp[j * H + hc + c4];
    }
    __syncthreads();
    int hl = (t & 15) * 4;
    int i0 = ic + (t >> 4) * 2;
    float4 av0 = *(const float4*)&a[(b * R + i0) * H + hc + hl];
    float4 av1 = *(const float4*)&a[(b * R + i0 + 1) * H + hc + hl];
    float4 ac0 = {0, 0, 0, 0}, ac1 = {0, 0, 0, 0};
    const float* Ar = A + i0 * R;
    #pragma unroll 4
    for (int j = 0; j < R; j++) {
        float4 bv = *(const float4*)&bbs[j * 64 + hl];
        float w0 = __ldg(&Ar[j]);
        float w1 = __ldg(&Ar[R + j]);
        ac0.x += w0 * fmaxf(av0.x + bv.x, 0.f);
        ac0.y += w0 * fmaxf(av0.y + bv.y, 0.f);
        ac0.z += w0 * fmaxf(av0.z + bv.z, 0.f);
        ac0.w += w0 * fmaxf(av0.w + bv.w, 0.f);
        ac1.x += w1 * fmaxf(av1.x + bv.x, 0.f);
        ac1.y += w1 * fmaxf(av1.y + bv.y, 0.f);
        ac1.z += w1 * fmaxf(av1.z + bv.z, 0.f);
        ac1.w += w1 * fmaxf(av1.w + bv.w, 0.f);
    }
    *(float4*)&out[(b * R + i0) * H + hc + hl]     = ac0;
    *(float4*)&out[(b * R + i0 + 1) * H + hc + hl] = ac1;
}

// ---------------------------------------------------------------------------
// h = LayerNorm(h + u) * g + beta
__global__ void ln_kernel(float* __restrict__ h, const float* __restrict__ u,
                          const float* __restrict__ gg, const float* __restrict__ bb) {
    __shared__ float red[8];
    int row = blockIdx.x, t = threadIdx.x;
    int o = row * H + t;
    float x = h[o] + u[o];
    float s = x;
    for (int k = 16; k; k >>= 1) s += __shfl_xor_sync(0xffffffffu, s, k);
    if ((t & 31) == 0) red[t >> 5] = s;
    __syncthreads();
    if (t < 32) {
        float v = (t < 8) ? red[t] : 0.f;
        for (int k = 4; k; k >>= 1) v += __shfl_xor_sync(0xffffffffu, v, k);
        if (t == 0) red[0] = v;
    }
    __syncthreads();
    float mu = red[0] * (1.f / H);
    __syncthreads();
    float d = x - mu;
    float q = d * d;
    for (int k = 16; k; k >>= 1) q += __shfl_xor_sync(0xffffffffu, q, k);
    if ((t & 31) == 0) red[t >> 5] = q;
    __syncthreads();
    if (t < 32) {
        float v = (t < 8) ? red[t] : 0.f;
        for (int k = 4; k; k >>= 1) v += __shfl_xor_sync(0xffffffffu, v, k);
        if (t == 0) red[0] = v;
    }
    __syncthreads();
    float var = red[0] * (1.f / H);
    h[o] = d * rsqrtf(var + 1e-5f) * gg[t] + bb[t];
}

// ---------------------------------------------------------------------------
// Multi-head attention for one (b, head, q-chunk of 16 rows).
__global__ __launch_bounds__(256) void attn_kernel(
    const float* __restrict__ q, const float* __restrict__ k,
    const float* __restrict__ v, float* __restrict__ ao)
{
    __shared__ float ks[128 * 65];
    __shared__ float qs[16 * 64];
    __shared__ float ls[16 * 128];
    int qc = blockIdx.x, head = blockIdx.y, b = blockIdx.z;
    int t = threadIdx.x;

    const float* kb = k + b * R * H + head * DH;
    for (int idx = t; idx < 128 * 64; idx += 256) {
        int j = idx >> 6, d = idx & 63;
        ks[j * 65 + d] = kb[j * H + d];
    }
    const float* qb = q + (b * R + qc * 16) * H + head * DH;
    for (int idx = t; idx < 16 * 64; idx += 256) {
        int r = idx >> 6, d = idx & 63;
        qs[r * 64 + d] = qb[r * H + d];
    }
    __syncthreads();

    {   // logits
        int j = t & 127, g = t >> 7;
        float acc[8];
        #pragma unroll
        for (int r = 0; r < 8; r++) acc[r] = 0.f;
        for (int d = 0; d < 64; d++) {
            float kv = ks[j * 65 + d];
            #pragma unroll
            for (int r = 0; r < 8; r++) acc[r] += qs[(g * 8 + r) * 64 + d] * kv;
        }
        #pragma unroll
        for (int r = 0; r < 8; r++) ls[(g * 8 + r) * 128 + j] = acc[r] * 0.125f;
    }
    __syncthreads();

    {   // row softmax
        int qr = t >> 4, jc = t & 15;
        float e[8]; float mx = -3e38f;
        #pragma unroll
        for (int jj = 0; jj < 8; jj++) {
            e[jj] = ls[qr * 128 + jc * 8 + jj];
            mx = fmaxf(mx, e[jj]);
        }
        for (int o = 8; o; o >>= 1) mx = fmaxf(mx, __shfl_xor_sync(0xffffffffu, mx, o));
        float s = 0.f;
        #pragma unroll
        for (int jj = 0; jj < 8; jj++) { e[jj] = expf(e[jj] - mx); s += e[jj]; }
        for (int o = 8; o; o >>= 1) s += __shfl_xor_sync(0xffffffffu, s, o);
        float inv = 1.f / s;
        #pragma unroll
        for (int jj = 0; jj < 8; jj++) ls[qr * 128 + jc * 8 + jj] = e[jj] * inv;
    }
    float* vs = ks;
    const float* vb = v + b * R * H + head * DH;
    for (int idx = t; idx < 128 * 64; idx += 256) {
        int j = idx >> 6, d = idx & 63;
        vs[j * 64 + d] = vb[j * H + d];
    }
    __syncthreads();

    {   // out = P @ V
        int qr = t >> 4, d4 = (t & 15) * 4;
        float4 acc = {0, 0, 0, 0};
        for (int j = 0; j < 128; j++) {
            float p = ls[qr * 128 + j];
            float4 vv = *(const float4*)&vs[j * 64 + d4];
            acc.x += p * vv.x; acc.y += p * vv.y;
            acc.z += p * vv.z; acc.w += p * vv.w;
        }
        *(float4*)&ao[(b * R + qc * 16 + qr) * H + head * DH + d4] = acc;
    }
}

// ---------------------------------------------------------------------------
// abar = mean_r ao; g = abar@Wo + bo; t = relu(g@roW1+rob1); logits; softmax.
__global__ void readout_kernel(const float* __restrict__ ao,
                               const float* __restrict__ Wo, const float* __restrict__ bo,
                               const float* __restrict__ roW1, const float* __restrict__ rob1,
                               const float* __restrict__ roW2, const float* __restrict__ rob2,
                               float* __restrict__ out) {
    __shared__ float s0[H], s1[H];
    __shared__ float red[8];
    int b = blockIdx.x, t = threadIdx.x;
    {
        float s = 0.f;
        const float* ap = ao + b * R * H + t;
        for (int r = 0; r < R; r++) s += ap[r * H];
        s0[t] = s * (1.f / R);
    }
    __syncthreads();
    float acc = bo[t];
    #pragma unroll 8
    for (int k = 0; k < H; k++) acc += s0[k] * Wo[k * H + t];
    s1[t] = acc;
    __syncthreads();
    acc = rob1[t];
    #pragma unroll 8
    for (int k = 0; k < H; k++) acc += s1[k] * roW1[k * H + t];
    __syncthreads();
    s0[t] = fmaxf(acc, 0.f);
    __syncthreads();
    float lg = -3e38f;
    if (t < R) {
        lg = rob2[t];
        #pragma unroll 8
        for (int k = 0; k < H; k++) lg += s0[k] * roW2[k * R + t];
    }
    float m = lg;
    for (int k = 16; k; k >>= 1) m = fmaxf(m, __shfl_xor_sync(0xffffffffu, m, k));
    if ((t & 31) == 0) red[t >> 5] = m;
    __syncthreads();
    if (t < 32) {
        float v = (t < 8) ? red[t] : -3e38f;
        for (int k = 4; k; k >>= 1) v = fmaxf(v, __shfl_xor_sync(0xffffffffu, v, k));
        if (t == 0) red[0] = v;
    }
    __syncthreads();
    float mx = red[0];
    __syncthreads();
    float e = (t < R) ? expf(lg - mx) : 0.f;
    float s = e;
    for (int k = 16; k; k >>= 1) s += __shfl_xor_sync(0xffffffffu, s, k);
    if ((t & 31) == 0) red[t >> 5] = s;
    __syncthreads();
    if (t < 32) {
        float v = (t < 8) ? red[t] : 0.f;
        for (int k = 4; k; k >>= 1) v += __shfl_xor_sync(0xffffffffu, v, k);
        if (t == 0) red[0] = v;
    }
    __syncthreads();
    float sum = red[0];
    if (t < R) out[b * R + t] = e / sum;
}

// ---------------------------------------------------------------------------
static inline GemmJob mkjob(const float* A, const float* W, float* C,
                            const float* bias = nullptr, const float* rowv = nullptr,
                            const float* colv = nullptr, const float* addend = nullptr,
                            int relu = 0) {
    GemmJob j;
    j.A = A; j.W = W; j.bias = bias; j.rowv = rowv; j.colv = colv;
    j.addend = addend; j.C = C; j.relu = relu;
    return j;
}

extern "C" void kernel_launch(void* const* d_in, const int* in_sizes, int n_in,
                              void* d_out, int out_size) {
    const float* x       = (const float*)d_in[0];
    const float* We      = (const float*)d_in[1];
    const float* be      = (const float*)d_in[2];
    const float* msg_W1  = (const float*)d_in[3];
    const float* msg_b1  = (const float*)d_in[4];
    const float* msg_W2  = (const float*)d_in[5];
    const float* msg_b2  = (const float*)d_in[6];
    const float* upd_W1  = (const float*)d_in[7];
    const float* upd_b1  = (const float*)d_in[8];
    const float* upd_W2  = (const float*)d_in[9];
    const float* upd_b2  = (const float*)d_in[10];
    const float* ln_g    = (const float*)d_in[11];
    const float* ln_b    = (const float*)d_in[12];
    const float* rule_adj= (const float*)d_in[13];
    const float* Wq      = (const float*)d_in[14];
    const float* bq      = (const float*)d_in[15];
    const float* Wk      = (const float*)d_in[16];
    const float* bk      = (const float*)d_in[17];
    const float* Wv      = (const float*)d_in[18];
    const float* bv      = (const float*)d_in[19];
    const float* Wo      = (const float*)d_in[20];
    const float* bo      = (const float*)d_in[21];
    const float* roW1    = (const float*)d_in[22];
    const float* rob1    = (const float*)d_in[23];
    const float* roW2    = (const float*)d_in[24];
    const float* rob2    = (const float*)d_in[25];
    float* out = (float*)d_out;

    float* base = nullptr;
    cudaGetSymbolAddress((void**)&base, g_buf);
    float* hb    = base + OFF_H;
    float* aact  = base + OFF_AACT;
    float* bbb   = base + OFF_BB;
    float* aggb  = base + OFF_AGG;
    float* hub   = base + OFF_HU;
    float* upreb = base + OFF_UPRE;
    float* ub    = base + OFF_U;
    float* qb    = base + OFF_Q;
    float* kb    = base + OFF_K;
    float* vb    = base + OFF_V;
    float* aob   = base + OFF_AO;
    float* Ab    = base + OFF_ADJ;
    float* rsb   = base + OFF_RS;
    float* w2ub  = base + OFF_W2U;
    float* c2b   = base + OFF_C2;

    const int M = B * R;  // 1024
    dim3 g44(4, M / 64, 3);     // fused-3 wide GEMM: 192 CTAs
    dim3 g1(4, M / 32);         // single-job GEMM: 128 CTAs

    setup_kernel<<<123, 256>>>(rule_adj, Ab, rsb, x, We, be, hb,
                               msg_b2, msg_W2, upd_W1, w2ub, c2b);

    for (int l = 0; l < L; l++) {
        const float* W1a = msg_W1 + l * 2 * HH;
        const float* W1b = W1a + HH;
        // fused: aact = h@W1a ; bb = h@W1b + b1 ; hu = h@Wu1a + b1u + rs*c2
        gemm44_kernel<<<g44, 256>>>(
            mkjob(hb, W1a, aact),
            mkjob(hb, W1b, bbb, msg_b1 + l * H),
            mkjob(hb, upd_W1 + l * 2 * HH, hub, upd_b1 + l * H, rsb, c2b + l * H));
        agg_kernel<<<dim3(4, 4, B), 256>>>(aact, bbb, Ab, aggb);
        // upre = relu(agg@W2u + hu)
        gemm1_kernel<<<g1, 256>>>(
            mkjob(aggb, w2ub + l * HH, upreb, nullptr, nullptr, nullptr, hub, 1));
        // u = upre@Wu2 + b2u
        gemm1_kernel<<<g1, 256>>>(
            mkjob(upreb, upd_W2 + l * HH, ub, upd_b2 + l * H));
        ln_kernel<<<M, H>>>(hb, ub, ln_g + l * H, ln_b + l * H);
    }

    // fused q/k/v
    gemm44_kernel<<<g44, 256>>>(
        mkjob(hb, Wq, qb, bq),
        mkjob(hb, Wk, kb, bk),
        mkjob(hb, Wv, vb, bv));
    attn_kernel<<<dim3(R / 16, NH, B), 256>>>(qb, kb, vb, aob);
    readout_kernel<<<B, H>>>(aob, Wo, bo, roW1, rob1, roW2, rob2, out);
    (void)in_sizes; (void)n_in; (void)out_size;
}